// round 2
// baseline (speedup 1.0000x reference)
#include <cuda_runtime.h>
#include <cstdint>
#include <math_constants.h>

// Problem constants (from reference): feat [N, C, 16, 8], scoremap [N, 13, 16, 8]
#define KP        13
#define HW        128     // 16*8 spatial
#define SP        64      // spatial pairs (f32x2 packing)
#define CPB       128     // channels per block
#define THREADS   128
#define FPAD      1       // float2 padding per smem row

// ---------- f32x2 helpers (Blackwell packed fp32) ----------
__device__ __forceinline__ unsigned long long pack2(float a, float b) {
    unsigned long long r;
    asm("mov.b64 %0, {%1, %2};" : "=l"(r) : "f"(a), "f"(b));
    return r;
}
__device__ __forceinline__ float2 unpack2(unsigned long long v) {
    float2 f;
    asm("mov.b64 {%0, %1}, %2;" : "=f"(f.x), "=f"(f.y) : "l"(v));
    return f;
}
__device__ __forceinline__ unsigned long long fma2(unsigned long long a,
                                                   unsigned long long b,
                                                   unsigned long long c) {
    unsigned long long d;
    asm("fma.rn.f32x2 %0, %1, %2, %3;" : "=l"(d) : "l"(a), "l"(b), "l"(c));
    return d;
}
__device__ __forceinline__ unsigned long long add2(unsigned long long a,
                                                   unsigned long long b) {
    unsigned long long d;
    asm("add.rn.f32x2 %0, %1, %2;" : "=l"(d) : "l"(a), "l"(b));
    return d;
}

// smem: [ score2: KP*SP float2 ][ feat2: SP rows x (CPB+FPAD) float2 ]
#define SMEM_F2_COUNT (KP * SP + SP * (CPB + FPAD))
#define SMEM_BYTES    (SMEM_F2_COUNT * (int)sizeof(float2))

__global__ __launch_bounds__(THREADS, 3)
void horeid_kernel(const float* __restrict__ feat,
                   const float* __restrict__ score,
                   const float* __restrict__ conf,
                   float* __restrict__ out_feat,   // [N, 14, C]
                   float* __restrict__ out_conf,   // [N, 14]
                   int C)
{
    extern __shared__ float2 smem[];
    float2* s_sc = smem;                 // [KP][SP]
    float2* s_ft = smem + KP * SP;       // [SP][CPB+FPAD]

    const int tid = threadIdx.x;
    const int n   = blockIdx.y;
    const int c0  = blockIdx.x * CPB;

    // ---- fold tiny conf normalization into one thread of blockIdx.x==0 ----
    if (blockIdx.x == 0 && tid == 0) {
        const float* cp = conf + (size_t)n * KP;
        float s = 0.0f;
        #pragma unroll
        for (int k = 0; k < KP; k++) s += fabsf(cp[k]);
        s = fmaxf(s, 1e-12f);
        float* oc = out_conf + (size_t)n * (KP + 1);
        #pragma unroll
        for (int k = 0; k < KP; k++) oc[k] = cp[k] / s;
        oc[KP] = 1.0f;   // tail: 1.0 / max(|1.0|, eps)
    }

    // ---- stage scoremap[n] as packed spatial pairs: s_sc[k*SP + sp] ----
    const float2* g_sc = (const float2*)(score + (size_t)n * KP * HW);
    for (int i = tid; i < KP * SP; i += THREADS) s_sc[i] = g_sc[i];

    // ---- stage feat tile [CPB x HW] -> transposed [sp][c], coalesced float4 ----
    const float4* g4 = (const float4*)(feat + ((size_t)n * C + c0) * HW);
    #pragma unroll
    for (int i = 0; i < (CPB * HW / 4) / THREADS; i++) {     // 32 iters
        int idx = tid + i * THREADS;
        int cc  = idx >> 5;        // / (HW/4)
        int sq  = idx & 31;        // float4 index within row
        float4 v = g4[(size_t)cc * (HW / 4) + sq];
        s_ft[(2 * sq    ) * (CPB + FPAD) + cc] = make_float2(v.x, v.y);
        s_ft[(2 * sq + 1) * (CPB + FPAD) + cc] = make_float2(v.z, v.w);
    }
    __syncthreads();

    // ---- main accumulation: one channel per thread ----
    unsigned long long acc[KP];
    #pragma unroll
    for (int k = 0; k < KP; k++) acc[k] = 0ull;
    unsigned long long sum2 = 0ull;
    float mx = -CUDART_INF_F;
    const int c = tid;

    #pragma unroll 8
    for (int sp = 0; sp < SP; sp++) {
        float2 f = s_ft[sp * (CPB + FPAD) + c];
        unsigned long long fd = pack2(f.x, f.y);
        #pragma unroll
        for (int k = 0; k < KP; k++) {
            unsigned long long sc =
                *reinterpret_cast<const unsigned long long*>(&s_sc[k * SP + sp]);
            acc[k] = fma2(fd, sc, acc[k]);
        }
        sum2 = add2(sum2, fd);
        mx = fmaxf(mx, fmaxf(f.x, f.y));
    }

    // ---- epilogue: 13 local sums + (mean + max) global, write [n][j][c] ----
    float2 s = unpack2(sum2);
    float g = (s.x + s.y) * (1.0f / (float)HW) + mx;
    float* op = out_feat + ((size_t)n * (KP + 1)) * C + c0 + c;
    #pragma unroll
    for (int k = 0; k < KP; k++) {
        float2 a = unpack2(acc[k]);
        op[(size_t)k * C] = a.x + a.y;
    }
    op[(size_t)KP * C] = g;
}

extern "C" void kernel_launch(void* const* d_in, const int* in_sizes, int n_in,
                              void* d_out, int out_size)
{
    const float* feat  = (const float*)d_in[0];
    const float* score = (const float*)d_in[1];
    const float* conf  = (const float*)d_in[2];
    float* out = (float*)d_out;

    const int N = in_sizes[2] / KP;                 // 256
    const int C = in_sizes[0] / ((size_t)N * HW);   // 2048

    float* out_feat = out;
    float* out_conf = out + (size_t)N * (KP + 1) * C;

    cudaFuncSetAttribute(horeid_kernel,
                         cudaFuncAttributeMaxDynamicSharedMemorySize, SMEM_BYTES);

    dim3 grid(C / CPB, N);
    horeid_kernel<<<grid, THREADS, SMEM_BYTES>>>(feat, score, conf,
                                                 out_feat, out_conf, C);
}